// round 13
// baseline (speedup 1.0000x reference)
#include <cuda_runtime.h>
#include <cuda_fp16.h>
#include <cstdint>

#define B_ 8
#define L_ 1030
#define D_ 1024
#define H_ 16
#define M_ (B_*L_)          // 8240
#define WSZ (1024*1024)

typedef __half hf;

static const size_t OUT_ELEMS  = (size_t)M_ * D_;              // 8,437,760
static const size_t ATTN_ELEMS = (size_t)B_ * H_ * L_ * L_;    // 135,795,200

// Scratch (device globals)
__device__ float g_xn[M_*D_];               // exact LN output (seg_fix input)
__device__ hf g_xb[M_*D_];                  // fp16 LN output (GEMM A)
__device__ hf g_qb[M_*D_];                  // fp16 Q (pre-scaled 0.125)
__device__ hf g_kb[M_*D_];
__device__ hf g_vb[M_*D_];
__device__ hf g_aob[M_*D_];                 // fp16 attention output
__device__ hf g_wt[4*WSZ];                  // transposed fp16 weights [N][K]

// =======================================================================
// helpers
// =======================================================================
static __device__ __forceinline__ uint32_t smem_u32(const void* p) {
    uint32_t a;
    asm("{ .reg .u64 t; cvta.to.shared.u64 t, %1; cvt.u32.u64 %0, t; }"
        : "=r"(a) : "l"(p));
    return a;
}
static __device__ __forceinline__ void ldm4(uint32_t* r, uint32_t addr) {
    asm volatile("ldmatrix.sync.aligned.m8n8.x4.shared.b16 {%0,%1,%2,%3}, [%4];"
        : "=r"(r[0]), "=r"(r[1]), "=r"(r[2]), "=r"(r[3]) : "r"(addr));
}
static __device__ __forceinline__ void ldm4t(uint32_t* r, uint32_t addr) {
    asm volatile("ldmatrix.sync.aligned.m8n8.x4.trans.shared.b16 {%0,%1,%2,%3}, [%4];"
        : "=r"(r[0]), "=r"(r[1]), "=r"(r[2]), "=r"(r[3]) : "r"(addr));
}
static __device__ __forceinline__ void mma16816(float* c, const uint32_t* a,
                                                const uint32_t* b) {
    asm volatile("mma.sync.aligned.m16n8k16.row.col.f32.f16.f16.f32 "
        "{%0,%1,%2,%3}, {%4,%5,%6,%7}, {%8,%9}, {%0,%1,%2,%3};"
        : "+f"(c[0]), "+f"(c[1]), "+f"(c[2]), "+f"(c[3])
        : "r"(a[0]), "r"(a[1]), "r"(a[2]), "r"(a[3]), "r"(b[0]), "r"(b[1]));
}
static __device__ __forceinline__ void cpa(uint32_t dst, const void* src, int sz) {
    asm volatile("cp.async.cg.shared.global [%0], [%1], 16, %2;"
                 :: "r"(dst), "l"(src), "r"(sz));
}
static __device__ __forceinline__ void cpa_commit() {
    asm volatile("cp.async.commit_group;");
}
static __device__ __forceinline__ unsigned short h2u(hf v) {
    return __half_as_ushort(v);
}

// =======================================================================
// LayerNorm: writes exact f32 xn AND fp16 xb
// =======================================================================
__global__ void __launch_bounds__(256) ln_kernel(const float* __restrict__ x,
                                                 const float* __restrict__ gam,
                                                 const float* __restrict__ bet)
{
    int row = blockIdx.x;
    int t = threadIdx.x;
    const float4* xr = reinterpret_cast<const float4*>(x + (size_t)row * D_);
    float4 v = xr[t];
    float s  = v.x + v.y + v.z + v.w;
    float ss = v.x*v.x + v.y*v.y + v.z*v.z + v.w*v.w;
    __shared__ float rs[8], rss[8], stat[2];
    #pragma unroll
    for (int o = 16; o; o >>= 1) {
        s  += __shfl_xor_sync(0xffffffffu, s,  o);
        ss += __shfl_xor_sync(0xffffffffu, ss, o);
    }
    if ((t & 31) == 0) { rs[t >> 5] = s; rss[t >> 5] = ss; }
    __syncthreads();
    if (t == 0) {
        float S = 0.f, SS = 0.f;
        #pragma unroll
        for (int i = 0; i < 8; i++) { S += rs[i]; SS += rss[i]; }
        float mu  = S / (float)D_;
        float var = SS / (float)D_ - mu * mu;
        stat[0] = mu;
        stat[1] = rsqrtf(var + 1e-6f);
    }
    __syncthreads();
    float mu = stat[0], inv = stat[1];
    float4 g4 = reinterpret_cast<const float4*>(gam)[t];
    float4 b4 = reinterpret_cast<const float4*>(bet)[t];
    float4 o;
    o.x = (v.x - mu) * inv * g4.x + b4.x;
    o.y = (v.y - mu) * inv * g4.y + b4.y;
    o.z = (v.z - mu) * inv * g4.z + b4.z;
    o.w = (v.w - mu) * inv * g4.w + b4.w;
    size_t base = (size_t)row * D_ + t * 4;
    *reinterpret_cast<float4*>(g_xn + base) = o;
    *reinterpret_cast<ushort4*>(g_xb + base) = make_ushort4(
        h2u(__float2half_rn(o.x)), h2u(__float2half_rn(o.y)),
        h2u(__float2half_rn(o.z)), h2u(__float2half_rn(o.w)));
}

// =======================================================================
// transpose + convert, all 4 weights in one launch (z selects)
// =======================================================================
__global__ void __launch_bounds__(256) tconv4_kernel(const float* __restrict__ w0,
                                                     const float* __restrict__ w1,
                                                     const float* __restrict__ w2,
                                                     const float* __restrict__ w3)
{
    __shared__ float sm[32][33];
    int z = blockIdx.z;
    const float* W = (z == 0) ? w0 : (z == 1) ? w1 : (z == 2) ? w2 : w3;
    hf* tw = g_wt + (size_t)z * WSZ;
    int c0 = blockIdx.x * 32, r0 = blockIdx.y * 32;
    int tx = threadIdx.x & 31, ty = threadIdx.x >> 5;
    #pragma unroll
    for (int k = 0; k < 32; k += 8)
        sm[ty + k][tx] = W[(size_t)(r0 + ty + k) * 1024 + c0 + tx];
    __syncthreads();
    #pragma unroll
    for (int k = 0; k < 32; k += 8) {
        float v = sm[tx][ty + k];
        int n = c0 + ty + k, kk = r0 + tx;
        tw[(size_t)n * 1024 + kk] = __float2half_rn(v);
    }
}

// =======================================================================
// single-fp16 HMMA GEMM, cp.async double-buffered, BK=64.
// Tile 128x128, 8 warps (4 M x 2 N), warp tile 32x64.
// =======================================================================
#define GSTG 36864
__global__ void __launch_bounds__(256) mma_gemm(
    const hf* __restrict__ A, const hf* __restrict__ Bw_,
    float* __restrict__ Cf, const float* __restrict__ bias,
    const float* __restrict__ resid,
    hf* Q_b, hf* K_b, hf* V_b, int M)
{
    extern __shared__ char smem[];
    const uint32_t sb = smem_u32(smem);

    const int tid = threadIdx.x;
    const int wid = tid >> 5, lane = tid & 31;
    const int wm = wid & 3, wn = wid >> 2;
    const int m0 = blockIdx.y * 128, n0 = blockIdx.x * 128;
    const int z = blockIdx.z;

    const hf* Bw = Bw_ + (size_t)z * WSZ;
    hf* Ob = (z == 0) ? Q_b : (z == 1) ? K_b : V_b;
    const float scale = (z == 0) ? 0.125f : 1.0f;

    float acc[2][8][4];
    #pragma unroll
    for (int i = 0; i < 2; i++)
        #pragma unroll
        for (int j = 0; j < 8; j++)
            #pragma unroll
            for (int c = 0; c < 4; c++) acc[i][j][c] = 0.f;

    auto prefetch = [&](int kt, int stg) {
        uint32_t base = sb + stg * GSTG;
        #pragma unroll
        for (int t = 0; t < 4; t++) {
            int idx = tid + t * 256;
            int r = idx >> 3;
            int cb = (idx & 7) * 16;
            uint32_t so = (uint32_t)r * 144 + cb;
            int arow = m0 + r;
            int sz = (arow < M) ? 16 : 0;
            int ar = (arow < M) ? arow : 0;
            cpa(base + so, (const char*)(A + (size_t)ar * 1024 + kt) + cb, sz);
            cpa(base + 18432 + so, (const char*)(Bw + (size_t)(n0 + r) * 1024 + kt) + cb, 16);
        }
        cpa_commit();
    };

    prefetch(0, 0);

    for (int it = 0; it < 16; it++) {
        if (it + 1 < 16) {
            prefetch((it + 1) * 64, (it + 1) & 1);
            asm volatile("cp.async.wait_group 1;");
        } else {
            asm volatile("cp.async.wait_group 0;");
        }
        __syncthreads();

        uint32_t st = sb + (it & 1) * GSTG;
        uint32_t sA = st, sB = st + 18432;

        #pragma unroll
        for (int ks = 0; ks < 4; ks++) {
            uint32_t a_[2][4], b_[4][4];
            #pragma unroll
            for (int mt = 0; mt < 2; mt++) {
                int row = wm * 32 + mt * 16 + (lane & 15);
                uint32_t off = (uint32_t)row * 144 + ks * 32 + ((lane >> 4) << 4);
                ldm4(a_[mt], sA + off);
            }
            #pragma unroll
            for (int p = 0; p < 4; p++) {
                int row = wn * 64 + p * 16 + (lane & 7) + ((lane >> 4) & 1) * 8;
                uint32_t off = (uint32_t)row * 144 + ks * 32 + (((lane >> 3) & 1) << 4);
                ldm4(b_[p], sB + off);
            }
            #pragma unroll
            for (int mt = 0; mt < 2; mt++)
                #pragma unroll
                for (int nt = 0; nt < 8; nt++)
                    mma16816(acc[mt][nt], a_[mt], &b_[nt >> 1][(nt & 1) * 2]);
        }
        __syncthreads();
    }

    #pragma unroll
    for (int mt = 0; mt < 2; mt++) {
        #pragma unroll
        for (int half = 0; half < 2; half++) {
            int row = m0 + wm * 32 + mt * 16 + (lane >> 2) + half * 8;
            if (row >= M) continue;
            #pragma unroll
            for (int nt = 0; nt < 8; nt++) {
                int col = n0 + wn * 64 + nt * 8 + (lane & 3) * 2;
                float vx = acc[mt][nt][half * 2 + 0];
                float vy = acc[mt][nt][half * 2 + 1];
                size_t go = (size_t)row * 1024 + col;
                if (Cf) {
                    if (bias) { vx += bias[col]; vy += bias[col + 1]; }
                    float2 v2; v2.x = vx; v2.y = vy;
                    if (resid) {
                        float2 rv = *reinterpret_cast<const float2*>(resid + go);
                        v2.x += rv.x; v2.y += rv.y;
                    }
                    *reinterpret_cast<float2*>(Cf + go) = v2;
                } else {
                    *reinterpret_cast<ushort2*>(Ob + go) = make_ushort2(
                        h2u(__float2half_rn(vx * scale)),
                        h2u(__float2half_rn(vy * scale)));
                }
            }
        }
    }
}

// =======================================================================
// segment fix-up: rows l in [1027,1030) use weight set 1 (exact fp32)
// =======================================================================
__global__ void __launch_bounds__(256) seg_fix(const float* __restrict__ wq1,
                                               const float* __restrict__ wk1,
                                               const float* __restrict__ wv1)
{
    int which = blockIdx.y;
    const float* W = (which == 0) ? wq1 : (which == 1) ? wk1 : wv1;
    hf* Ob = (which == 0) ? g_qb : (which == 1) ? g_kb : g_vb;
    float scale = (which == 0) ? 0.125f : 1.0f;
    int batch = blockIdx.x / 3, s = blockIdx.x % 3;
    int row = batch * L_ + (L_ - 3) + s;

    __shared__ float xs[1024];
    for (int i = threadIdx.x; i < 1024; i += 256) xs[i] = g_xn[(size_t)row * 1024 + i];
    __syncthreads();

    float a[4] = {0.f, 0.f, 0.f, 0.f};
    const float* Wc = W + threadIdx.x;
    #pragma unroll 8
    for (int k = 0; k < 1024; k++) {
        float xv = xs[k];
        const float* wr = Wc + (size_t)k * 1024;
        a[0] += xv * wr[0];
        a[1] += xv * wr[256];
        a[2] += xv * wr[512];
        a[3] += xv * wr[768];
    }
    #pragma unroll
    for (int j = 0; j < 4; j++) {
        size_t off = (size_t)row * 1024 + threadIdx.x + j * 256;
        Ob[off] = __float2half_rn(a[j] * scale);
    }
}

// =======================================================================
// tensorized fused attention: 16 query rows / block, 2 CTAs per SM.
// Deferred-normalization softmax: phase1 tracks rowmax; conv pass computes
// e=exp(S-m) (stored fp16 P + f32 S) + register rowsums; O scaled by 1/sum
// at epilogue; attn written as e*inv in one final coalesced pass.
// smem (byte offsets): S 16x1032 f32 | Q 16x72 hf | KV 2x18432 | P 16x136 hf
//                      rowmaxp 16x8 | rowmax16 | rowsump 16x16 | inv 16
// =======================================================================
#define SST 1032
#define OFF_Q   66048
#define OFF_KV  68352
#define KVSTG   18432
#define OFF_P   105216
#define OFF_RMP 109568
#define OFF_RM16 110080
#define OFF_RSP 110144
#define OFF_INV 111168
#define ATTN_SMEM 111232
#define NTILE 9

__global__ void __launch_bounds__(256) attn_mma(float* __restrict__ attn_out)
{
    extern __shared__ char sm[];
    float* S = reinterpret_cast<float*>(sm);
    hf* Qb = reinterpret_cast<hf*>(sm + OFF_Q);
    hf* Pb = reinterpret_cast<hf*>(sm + OFF_P);
    float* rowmaxp  = reinterpret_cast<float*>(sm + OFF_RMP);
    float* rowmax16 = reinterpret_cast<float*>(sm + OFF_RM16);
    float* rowsump  = reinterpret_cast<float*>(sm + OFF_RSP);
    float* invs     = reinterpret_cast<float*>(sm + OFF_INV);
    float* Osm      = reinterpret_cast<float*>(sm + OFF_P);   // alias (P dead)
    const uint32_t uQ = smem_u32(Qb);
    const uint32_t uKV = smem_u32(sm + OFF_KV);
    const uint32_t uP = smem_u32(Pb);

    const int tid = threadIdx.x;
    const int wid = tid >> 5, lane = tid & 31;
    const int qt = blockIdx.x, h = blockIdx.y, b = blockIdx.z;
    const int q0 = qt * 16;
    const size_t headq = (size_t)b * L_ * 1024 + h * 64;

    auto prefetch_t = [&](const hf* src, int kt, int stg) {
        uint32_t base = uKV + stg * KVSTG;
        #pragma unroll
        for (int t = 0; t < 4; t++) {
            int idx = tid + t * 256;
            int r = idx >> 3;
            int cb = (idx & 7) * 16;
            int l = kt + r;
            int sz = (l < L_) ? 16 : 0;
            int lr = (l < L_) ? l : 0;
            cpa(base + (uint32_t)r * 144 + cb,
                (const char*)(src + headq + (size_t)lr * 1024) + cb, sz);
        }
        cpa_commit();
    };

    prefetch_t(g_kb, 0, 0);

    // ---- load Q (16 rows x 64, pre-scaled fp16) ----
    {
        int r = tid >> 4, c4 = (tid & 15) * 4;
        int l = q0 + r;
        ushort4 v = make_ushort4(0, 0, 0, 0);
        if (l < L_)
            v = *reinterpret_cast<const ushort4*>(g_qb + headq + (size_t)l * 1024 + c4);
        *reinterpret_cast<ushort4*>(Qb + r * 72 + c4) = v;
    }

    // ---- phase 1: S = Q.K^T, warp w covers cols [w*16, w*16+16) per tile ----
    float mx0 = -1e30f, mx1 = -1e30f;
    const int r0l = lane >> 2;
    for (int t9 = 0; t9 < NTILE; t9++) {
        if (t9 + 1 < NTILE) {
            prefetch_t(g_kb, (t9 + 1) * 128, (t9 + 1) & 1);
            asm volatile("cp.async.wait_group 1;");
        } else {
            asm volatile("cp.async.wait_group 0;");
        }
        __syncthreads();
        uint32_t uK = uKV + (t9 & 1) * KVSTG;
        int kt = t9 * 128;

        float acc[2][4];
        #pragma unroll
        for (int i = 0; i < 2; i++)
            #pragma unroll
            for (int c = 0; c < 4; c++) acc[i][c] = 0.f;

        #pragma unroll
        for (int ks = 0; ks < 4; ks++) {
            uint32_t q_[4], k_[4];
            {
                int row = lane & 15;
                uint32_t off = (uint32_t)row * 144 + ks * 32 + ((lane >> 4) << 4);
                ldm4(q_, uQ + off);
            }
            {
                int row = wid * 16 + (lane & 7) + ((lane >> 4) & 1) * 8;
                uint32_t off = (uint32_t)row * 144 + ks * 32 + (((lane >> 3) & 1) << 4);
                ldm4(k_, uK + off);
            }
            mma16816(acc[0], q_, &k_[0]);
            mma16816(acc[1], q_, &k_[2]);
        }

        #pragma unroll
        for (int nt = 0; nt < 2; nt++) {
            int col = kt + wid * 16 + nt * 8 + (lane & 3) * 2;
            if (col < L_)     S[r0l * SST + col]            = acc[nt][0];
            if (col + 1 < L_) S[r0l * SST + col + 1]        = acc[nt][1];
            if (col < L_)     S[(r0l + 8) * SST + col]      = acc[nt][2];
            if (col + 1 < L_) S[(r0l + 8) * SST + col + 1]  = acc[nt][3];
            mx0 = fmaxf(mx0, fmaxf(acc[nt][0], acc[nt][1]));
            mx1 = fmaxf(mx1, fmaxf(acc[nt][2], acc[nt][3]));
        }
        __syncthreads();
    }
    // quad reduce -> partial row maxima (m >= true max is safe: shift-invariant)
    mx0 = fmaxf(mx0, __shfl_xor_sync(0xffffffffu, mx0, 1));
    mx0 = fmaxf(mx0, __shfl_xor_sync(0xffffffffu, mx0, 2));
    mx1 = fmaxf(mx1, __shfl_xor_sync(0xffffffffu, mx1, 1));
    mx1 = fmaxf(mx1, __shfl_xor_sync(0xffffffffu, mx1, 2));
    if ((lane & 3) == 0) {
        rowmaxp[r0l * 8 + wid]       = mx0;
        rowmaxp[(r0l + 8) * 8 + wid] = mx1;
    }
    prefetch_t(g_vb, 0, 0);          // overlap V(0) with max reduce
    __syncthreads();
    if (tid < 16) {
        float m = -1e30f;
        #pragma unroll
        for (int j = 0; j < 8; j++) m = fmaxf(m, rowmaxp[tid * 8 + j]);
        rowmax16[tid] = m;
    }
    __syncthreads();

    // ---- phase 2: conv (exp into P/S, register sums) + PV mma ----
    const int cr = tid >> 4, cg = tid & 15;
    const float m = rowmax16[cr];
    float lsum = 0.f;
    const int wk = wid & 1, wn = wid >> 1;
    float acc2[2][4];
    #pragma unroll
    for (int i = 0; i < 2; i++)
        #pragma unroll
        for (int c = 0; c < 4; c++) acc2[i][c] = 0.f;

    for (int t9 = 0; t9 < NTILE; t9++) {
        if (t9 + 1 < NTILE) prefetch_t(g_vb, (t9 + 1) * 128, (t9 + 1) & 1);
        int kt = t9 * 128;
        #pragma unroll
        for (int i = 0; i < 8; i++) {
            int col = kt + cg * 8 + i;
            float e = 0.f;
            if (col < L_) {
                e = __expf(S[cr * SST + col] - m);
                S[cr * SST + col] = e;
                lsum += e;
            }
            Pb[cr * 136 + cg * 8 + i] = __float2half_rn(e);
        }
        if (t9 + 1 < NTILE) asm volatile("cp.async.wait_group 1;");
        else                asm volatile("cp.async.wait_group 0;");
        __syncthreads();
        uint32_t uV = uKV + (t9 & 1) * KVSTG;

        #pragma unroll
        for (int ks = 0; ks < 4; ks++) {
            uint32_t p_[4], v_[4];
            {
                int row = lane & 15;
                uint32_t off = (uint32_t)row * 272 + (wk * 4 + ks) * 32 + ((lane >> 4) << 4);
                ldm4(p_, uP + off);
            }
            {
                int row = wk * 64 + ks * 16 + (lane & 15);
                uint32_t off = (uint32_t)row * 144 + wn * 32 + ((lane >> 4) << 4);
                ldm4t(v_, uV + off);
            }
            mma16816(acc2[0], p_, &v_[0]);
            mma16816(acc2[1], p_, &v_[2]);
        }
        __syncthreads();
    }

    // ---- sums, cross-wk O reduce, outputs ----
    rowsump[cr * 16 + cg] = lsum;
    if (wk == 1) {
        #pragma unroll
        for (int nt = 0; nt < 2; nt++) {
            int c = wn * 16 + nt * 8 + (lane & 3) * 2;
            Osm[r0l * 64 + c]           = acc2[nt][0];
            Osm[r0l * 64 + c + 1]       = acc2[nt][1];
            Osm[(r0l + 8) * 64 + c]     = acc2[nt][2];
            Osm[(r0l + 8) * 64 + c + 1] = acc2[nt][3];
        }
    }
    __syncthreads();
    if (tid < 16) {
        float s = 0.f;
        #pragma unroll
        for (int j = 0; j < 16; j++) s += rowsump[tid * 16 + j];
        invs[tid] = 1.f / s;
    }
    __syncthreads();

    if (wk == 0) {
        #pragma unroll
        for (int half = 0; half < 2; half++) {
            int rr = r0l + half * 8;
            int l = q0 + rr;
            if (l >= L_) continue;
            float iv = invs[rr];
            #pragma unroll
            for (int nt = 0; nt < 2; nt++) {
                int d = wn * 16 + nt * 8 + (lane & 3) * 2;
                float ox = (acc2[nt][half * 2 + 0] + Osm[rr * 64 + d]) * iv;
                float oy = (acc2[nt][half * 2 + 1] + Osm[rr * 64 + d + 1]) * iv;
                *reinterpret_cast<ushort2*>(g_aob + headq + (size_t)l * 1024 + d) =
                    make_ushort2(h2u(__float2half_rn(ox)), h2u(__float2half_rn(oy)));
            }
        }
    }

    // ---- attn output: p = e * inv, coalesced (16 consecutive cols/half-warp) ----
    if (attn_out) {
        int l = q0 + cr;
        if (l < L_) {
            float iv = invs[cr];
            size_t abase = ((size_t)(b * H_ + h) * L_ + l) * L_;
            for (int it = 0; it < 65; it++) {
                int col = cg + it * 16;
                if (col < L_)
                    attn_out[abase + col] = S[cr * SST + col] * iv;
            }
        }
    }
}

// =======================================================================
// launch
// =======================================================================
extern "C" void kernel_launch(void* const* d_in, const int* in_sizes, int n_in,
                              void* d_out, int out_size)
{
    const float* x    = (const float*)d_in[0];
    const float* wq0  = (const float*)d_in[1];
    const float* wq1  = (const float*)d_in[2];
    const float* wk0  = (const float*)d_in[3];
    const float* wk1  = (const float*)d_in[4];
    const float* wv0  = (const float*)d_in[5];
    const float* wv1  = (const float*)d_in[6];
    const float* fc_w = (const float*)d_in[7];
    const float* fc_b = (const float*)d_in[8];
    const float* ln_g = (const float*)d_in[9];
    const float* ln_b = (const float*)d_in[10];
    float* out = (float*)d_out;

    hf *p_xb, *p_qb, *p_kb, *p_vb, *p_aob, *p_wt;
    cudaGetSymbolAddress((void**)&p_xb,  g_xb);
    cudaGetSymbolAddress((void**)&p_qb,  g_qb);
    cudaGetSymbolAddress((void**)&p_kb,  g_kb);
    cudaGetSymbolAddress((void**)&p_vb,  g_vb);
    cudaGetSymbolAddress((void**)&p_aob, g_aob);
    cudaGetSymbolAddress((void**)&p_wt,  g_wt);

    float* attn_ptr = ((size_t)out_size >= OUT_ELEMS + ATTN_ELEMS)
                        ? (out + OUT_ELEMS) : nullptr;

    cudaFuncSetAttribute(mma_gemm, cudaFuncAttributeMaxDynamicSharedMemorySize, 2 * GSTG);
    cudaFuncSetAttribute(attn_mma, cudaFuncAttributeMaxDynamicSharedMemorySize, ATTN_SMEM);

    // 1) LayerNorm (f32 + fp16)
    ln_kernel<<<M_, 256>>>(x, ln_g, ln_b);

    // 2) transpose+convert all 4 weights in one launch
    tconv4_kernel<<<dim3(32, 32, 4), 256>>>(wq0, wk0, wv0, fc_w);

    // 3) fused QKV projections (fp16 epilogue, Q pre-scaled)
    dim3 gq(8, (M_ + 127) / 128, 3);
    mma_gemm<<<gq, 256, 2 * GSTG>>>(p_xb, p_wt, nullptr, nullptr, nullptr,
                                    p_qb, p_kb, p_vb, M_);

    // 4) exact fp32 fix for the 24 weight-set-1 rows
    seg_fix<<<dim3(24, 3), 256>>>(wq1, wk1, wv1);

    // 5) tensorized attention (16-row blocks, 2 CTAs/SM)
    attn_mma<<<dim3((L_ + 15) / 16, H_, B_), 256, ATTN_SMEM>>>(attn_ptr);

    // 6) FC (+bias+residual) -> out
    dim3 gf(8, (M_ + 127) / 128, 1);
    mma_gemm<<<gf, 256, 2 * GSTG>>>(p_aob, p_wt + 3 * (size_t)WSZ,
                                    out, fc_b, x,
                                    nullptr, nullptr, nullptr, M_);
}

// round 14
// speedup vs baseline: 1.2790x; 1.2790x over previous
#include <cuda_runtime.h>
#include <cuda_fp16.h>
#include <cstdint>

#define B_ 8
#define L_ 1030
#define D_ 1024
#define H_ 16
#define M_ (B_*L_)          // 8240
#define WSZ (1024*1024)

typedef __half hf;

static const size_t OUT_ELEMS  = (size_t)M_ * D_;              // 8,437,760
static const size_t ATTN_ELEMS = (size_t)B_ * H_ * L_ * L_;    // 135,795,200

// Scratch (device globals)
__device__ float g_xn[M_*D_];               // exact LN output (seg_fix input)
__device__ hf g_xb[M_*D_];                  // fp16 LN output (GEMM A)
__device__ hf g_qb[M_*D_];                  // fp16 Q (pre-scaled 0.125)
__device__ hf g_kb[M_*D_];
__device__ hf g_vb[M_*D_];
__device__ hf g_aob[M_*D_];                 // fp16 attention output
__device__ hf g_wt[4*WSZ];                  // transposed fp16 weights [N][K]

// =======================================================================
// helpers
// =======================================================================
static __device__ __forceinline__ uint32_t smem_u32(const void* p) {
    uint32_t a;
    asm("{ .reg .u64 t; cvta.to.shared.u64 t, %1; cvt.u32.u64 %0, t; }"
        : "=r"(a) : "l"(p));
    return a;
}
static __device__ __forceinline__ void ldm4(uint32_t* r, uint32_t addr) {
    asm volatile("ldmatrix.sync.aligned.m8n8.x4.shared.b16 {%0,%1,%2,%3}, [%4];"
        : "=r"(r[0]), "=r"(r[1]), "=r"(r[2]), "=r"(r[3]) : "r"(addr));
}
static __device__ __forceinline__ void ldm4t(uint32_t* r, uint32_t addr) {
    asm volatile("ldmatrix.sync.aligned.m8n8.x4.trans.shared.b16 {%0,%1,%2,%3}, [%4];"
        : "=r"(r[0]), "=r"(r[1]), "=r"(r[2]), "=r"(r[3]) : "r"(addr));
}
static __device__ __forceinline__ void mma16816(float* c, const uint32_t* a,
                                                const uint32_t* b) {
    asm volatile("mma.sync.aligned.m16n8k16.row.col.f32.f16.f16.f32 "
        "{%0,%1,%2,%3}, {%4,%5,%6,%7}, {%8,%9}, {%0,%1,%2,%3};"
        : "+f"(c[0]), "+f"(c[1]), "+f"(c[2]), "+f"(c[3])
        : "r"(a[0]), "r"(a[1]), "r"(a[2]), "r"(a[3]), "r"(b[0]), "r"(b[1]));
}
static __device__ __forceinline__ void cpa(uint32_t dst, const void* src, int sz) {
    asm volatile("cp.async.cg.shared.global [%0], [%1], 16, %2;"
                 :: "r"(dst), "l"(src), "r"(sz));
}
static __device__ __forceinline__ void cpa_commit() {
    asm volatile("cp.async.commit_group;");
}
static __device__ __forceinline__ unsigned short h2u(hf v) {
    return __half_as_ushort(v);
}

// =======================================================================
// LayerNorm: writes exact f32 xn AND fp16 xb
// =======================================================================
__global__ void __launch_bounds__(256) ln_kernel(const float* __restrict__ x,
                                                 const float* __restrict__ gam,
                                                 const float* __restrict__ bet)
{
    int row = blockIdx.x;
    int t = threadIdx.x;
    const float4* xr = reinterpret_cast<const float4*>(x + (size_t)row * D_);
    float4 v = xr[t];
    float s  = v.x + v.y + v.z + v.w;
    float ss = v.x*v.x + v.y*v.y + v.z*v.z + v.w*v.w;
    __shared__ float rs[8], rss[8], stat[2];
    #pragma unroll
    for (int o = 16; o; o >>= 1) {
        s  += __shfl_xor_sync(0xffffffffu, s,  o);
        ss += __shfl_xor_sync(0xffffffffu, ss, o);
    }
    if ((t & 31) == 0) { rs[t >> 5] = s; rss[t >> 5] = ss; }
    __syncthreads();
    if (t == 0) {
        float S = 0.f, SS = 0.f;
        #pragma unroll
        for (int i = 0; i < 8; i++) { S += rs[i]; SS += rss[i]; }
        float mu  = S / (float)D_;
        float var = SS / (float)D_ - mu * mu;
        stat[0] = mu;
        stat[1] = rsqrtf(var + 1e-6f);
    }
    __syncthreads();
    float mu = stat[0], inv = stat[1];
    float4 g4 = reinterpret_cast<const float4*>(gam)[t];
    float4 b4 = reinterpret_cast<const float4*>(bet)[t];
    float4 o;
    o.x = (v.x - mu) * inv * g4.x + b4.x;
    o.y = (v.y - mu) * inv * g4.y + b4.y;
    o.z = (v.z - mu) * inv * g4.z + b4.z;
    o.w = (v.w - mu) * inv * g4.w + b4.w;
    size_t base = (size_t)row * D_ + t * 4;
    *reinterpret_cast<float4*>(g_xn + base) = o;
    *reinterpret_cast<ushort4*>(g_xb + base) = make_ushort4(
        h2u(__float2half_rn(o.x)), h2u(__float2half_rn(o.y)),
        h2u(__float2half_rn(o.z)), h2u(__float2half_rn(o.w)));
}

// =======================================================================
// transpose + convert, all 4 weights in one launch (z selects)
// =======================================================================
__global__ void __launch_bounds__(256) tconv4_kernel(const float* __restrict__ w0,
                                                     const float* __restrict__ w1,
                                                     const float* __restrict__ w2,
                                                     const float* __restrict__ w3)
{
    __shared__ float sm[32][33];
    int z = blockIdx.z;
    const float* W = (z == 0) ? w0 : (z == 1) ? w1 : (z == 2) ? w2 : w3;
    hf* tw = g_wt + (size_t)z * WSZ;
    int c0 = blockIdx.x * 32, r0 = blockIdx.y * 32;
    int tx = threadIdx.x & 31, ty = threadIdx.x >> 5;
    #pragma unroll
    for (int k = 0; k < 32; k += 8)
        sm[ty + k][tx] = W[(size_t)(r0 + ty + k) * 1024 + c0 + tx];
    __syncthreads();
    #pragma unroll
    for (int k = 0; k < 32; k += 8) {
        float v = sm[tx][ty + k];
        int n = c0 + ty + k, kk = r0 + tx;
        tw[(size_t)n * 1024 + kk] = __float2half_rn(v);
    }
}

// =======================================================================
// single-fp16 HMMA GEMM, cp.async double-buffered, BK=64.
// Tile 128x128, 8 warps (4 M x 2 N), warp tile 32x64.
// =======================================================================
#define GSTG 36864
__global__ void __launch_bounds__(256) mma_gemm(
    const hf* __restrict__ A, const hf* __restrict__ Bw_,
    float* __restrict__ Cf, const float* __restrict__ bias,
    const float* __restrict__ resid,
    hf* Q_b, hf* K_b, hf* V_b, int M)
{
    extern __shared__ char smem[];
    const uint32_t sb = smem_u32(smem);

    const int tid = threadIdx.x;
    const int wid = tid >> 5, lane = tid & 31;
    const int wm = wid & 3, wn = wid >> 2;
    const int m0 = blockIdx.y * 128, n0 = blockIdx.x * 128;
    const int z = blockIdx.z;

    const hf* Bw = Bw_ + (size_t)z * WSZ;
    hf* Ob = (z == 0) ? Q_b : (z == 1) ? K_b : V_b;
    const float scale = (z == 0) ? 0.125f : 1.0f;

    float acc[2][8][4];
    #pragma unroll
    for (int i = 0; i < 2; i++)
        #pragma unroll
        for (int j = 0; j < 8; j++)
            #pragma unroll
            for (int c = 0; c < 4; c++) acc[i][j][c] = 0.f;

    auto prefetch = [&](int kt, int stg) {
        uint32_t base = sb + stg * GSTG;
        #pragma unroll
        for (int t = 0; t < 4; t++) {
            int idx = tid + t * 256;
            int r = idx >> 3;
            int cb = (idx & 7) * 16;
            uint32_t so = (uint32_t)r * 144 + cb;
            int arow = m0 + r;
            int sz = (arow < M) ? 16 : 0;
            int ar = (arow < M) ? arow : 0;
            cpa(base + so, (const char*)(A + (size_t)ar * 1024 + kt) + cb, sz);
            cpa(base + 18432 + so, (const char*)(Bw + (size_t)(n0 + r) * 1024 + kt) + cb, 16);
        }
        cpa_commit();
    };

    prefetch(0, 0);

    for (int it = 0; it < 16; it++) {
        if (it + 1 < 16) {
            prefetch((it + 1) * 64, (it + 1) & 1);
            asm volatile("cp.async.wait_group 1;");
        } else {
            asm volatile("cp.async.wait_group 0;");
        }
        __syncthreads();

        uint32_t st = sb + (it & 1) * GSTG;
        uint32_t sA = st, sB = st + 18432;

        #pragma unroll
        for (int ks = 0; ks < 4; ks++) {
            uint32_t a_[2][4], b_[4][4];
            #pragma unroll
            for (int mt = 0; mt < 2; mt++) {
                int row = wm * 32 + mt * 16 + (lane & 15);
                uint32_t off = (uint32_t)row * 144 + ks * 32 + ((lane >> 4) << 4);
                ldm4(a_[mt], sA + off);
            }
            #pragma unroll
            for (int p = 0; p < 4; p++) {
                int row = wn * 64 + p * 16 + (lane & 7) + ((lane >> 4) & 1) * 8;
                uint32_t off = (uint32_t)row * 144 + ks * 32 + (((lane >> 3) & 1) << 4);
                ldm4(b_[p], sB + off);
            }
            #pragma unroll
            for (int mt = 0; mt < 2; mt++)
                #pragma unroll
                for (int nt = 0; nt < 8; nt++)
                    mma16816(acc[mt][nt], a_[mt], &b_[nt >> 1][(nt & 1) * 2]);
        }
        __syncthreads();
    }

    #pragma unroll
    for (int mt = 0; mt < 2; mt++) {
        #pragma unroll
        for (int half = 0; half < 2; half++) {
            int row = m0 + wm * 32 + mt * 16 + (lane >> 2) + half * 8;
            if (row >= M) continue;
            #pragma unroll
            for (int nt = 0; nt < 8; nt++) {
                int col = n0 + wn * 64 + nt * 8 + (lane & 3) * 2;
                float vx = acc[mt][nt][half * 2 + 0];
                float vy = acc[mt][nt][half * 2 + 1];
                size_t go = (size_t)row * 1024 + col;
                if (Cf) {
                    if (bias) { vx += bias[col]; vy += bias[col + 1]; }
                    float2 v2; v2.x = vx; v2.y = vy;
                    if (resid) {
                        float2 rv = *reinterpret_cast<const float2*>(resid + go);
                        v2.x += rv.x; v2.y += rv.y;
                    }
                    *reinterpret_cast<float2*>(Cf + go) = v2;
                } else {
                    *reinterpret_cast<ushort2*>(Ob + go) = make_ushort2(
                        h2u(__float2half_rn(vx * scale)),
                        h2u(__float2half_rn(vy * scale)));
                }
            }
        }
    }
}

// =======================================================================
// seg_fix2: recompute the 24 weight-set-1 rows (exact fp32 GEMV).
// grid (32 col-chunks x 3 weights); all 24 x-rows staged in 96KB smem;
// warp w handles rows 3w..3w+2, 32 coalesced cols; W read exactly once.
// =======================================================================
#define SEG_SMEM 98304
__global__ void __launch_bounds__(256) seg_fix2(const float* __restrict__ wq1,
                                                const float* __restrict__ wk1,
                                                const float* __restrict__ wv1)
{
    extern __shared__ float xs[];   // [24][1024]
    int which = blockIdx.y;
    const float* W = (which == 0) ? wq1 : (which == 1) ? wk1 : wv1;
    hf* Ob = (which == 0) ? g_qb : (which == 1) ? g_kb : g_vb;
    float scale = (which == 0) ? 0.125f : 1.0f;
    const int tid = threadIdx.x;

    // stage all 24 fix rows of g_xn (24 x 256 float4)
    for (int i = tid; i < 24 * 256; i += 256) {
        int rr = i >> 8, c4 = i & 255;
        int batch = rr / 3, s = rr % 3;
        size_t grow = (size_t)(batch * L_ + (L_ - 3) + s) * 1024;
        reinterpret_cast<float4*>(xs)[rr * 256 + c4] =
            *reinterpret_cast<const float4*>(g_xn + grow + c4 * 4);
    }
    __syncthreads();

    const int warp = tid >> 5, lane = tid & 31;
    const int col = blockIdx.x * 32 + lane;
    const int r0 = warp * 3;
    const float* xs0 = xs + (r0 + 0) * 1024;
    const float* xs1 = xs + (r0 + 1) * 1024;
    const float* xs2 = xs + (r0 + 2) * 1024;
    float a0 = 0.f, a1 = 0.f, a2 = 0.f;
    #pragma unroll 8
    for (int k = 0; k < 1024; k++) {
        float wv = W[(size_t)k * 1024 + col];
        a0 += xs0[k] * wv;
        a1 += xs1[k] * wv;
        a2 += xs2[k] * wv;
    }
    #pragma unroll
    for (int j = 0; j < 3; j++) {
        int rr = r0 + j;
        int batch = rr / 3, s = rr % 3;
        float v = ((j == 0) ? a0 : (j == 1) ? a1 : a2) * scale;
        size_t off = (size_t)(batch * L_ + (L_ - 3) + s) * 1024 + col;
        Ob[off] = __float2half_rn(v);
    }
}

// =======================================================================
// tensorized fused attention (round-10 version: 32 query rows, 8 warps 2Mx4N,
// cp.async double-buffered K/V, fp16 single-term)
// =======================================================================
#define SST 1032
#define OFF_Q  132096
#define OFF_KV (OFF_Q + 32*72*2)            // 136704
#define KVSTG  18432
#define OFF_P  (OFF_KV + 2*KVSTG)           // 173568
#define ATTN_SMEM (OFF_P + 32*136*2)        // 182272
#define NTILE 9

__global__ void __launch_bounds__(256) attn_mma(float* __restrict__ attn_out)
{
    extern __shared__ char sm[];
    float* S = reinterpret_cast<float*>(sm);
    hf* Qb = reinterpret_cast<hf*>(sm + OFF_Q);
    hf* Pb = reinterpret_cast<hf*>(sm + OFF_P);
    const uint32_t uQ = smem_u32(Qb);
    const uint32_t uKV = smem_u32(sm + OFF_KV);
    const uint32_t uP = smem_u32(Pb);

    const int tid = threadIdx.x;
    const int wid = tid >> 5, lane = tid & 31;
    const int wm = wid & 1, wn = wid >> 1;      // 2 (M) x 4 (N)
    const int qt = blockIdx.x, h = blockIdx.y, b = blockIdx.z;
    const int q0 = qt * 32;
    const size_t headq = (size_t)b * L_ * 1024 + h * 64;

    auto prefetch_t = [&](const hf* src, int kt, int stg) {
        uint32_t base = uKV + stg * KVSTG;
        #pragma unroll
        for (int t = 0; t < 4; t++) {
            int idx = tid + t * 256;
            int r = idx >> 3;
            int cb = (idx & 7) * 16;
            int l = kt + r;
            int sz = (l < L_) ? 16 : 0;
            int lr = (l < L_) ? l : 0;
            cpa(base + (uint32_t)r * 144 + cb,
                (const char*)(src + headq + (size_t)lr * 1024) + cb, sz);
        }
        cpa_commit();
    };

    prefetch_t(g_kb, 0, 0);

    // ---- load Q (pre-scaled fp16) ----
    #pragma unroll
    for (int t = 0; t < 2; t++) {
        int idx = tid + t * 256;
        int r = idx >> 4, c4 = (idx & 15) * 4;
        int l = q0 + r;
        ushort4 v = make_ushort4(0, 0, 0, 0);
        if (l < L_)
            v = *reinterpret_cast<const ushort4*>(g_qb + headq + (size_t)l * 1024 + c4);
        *reinterpret_cast<ushort4*>(Qb + r * 72 + c4) = v;
    }

    // ---- phase 1: S = Q.K^T ----
    for (int t9 = 0; t9 < NTILE; t9++) {
        if (t9 + 1 < NTILE) {
            prefetch_t(g_kb, (t9 + 1) * 128, (t9 + 1) & 1);
            asm volatile("cp.async.wait_group 1;");
        } else {
            asm volatile("cp.async.wait_group 0;");
        }
        __syncthreads();
        uint32_t uK = uKV + (t9 & 1) * KVSTG;
        int kt = t9 * 128;

        float acc[4][4];
        #pragma unroll
        for (int i = 0; i < 4; i++)
            #pragma unroll
            for (int c = 0; c < 4; c++) acc[i][c] = 0.f;

        #pragma unroll
        for (int ks = 0; ks < 4; ks++) {
            uint32_t q_[4], k_[2][4];
            {
                int row = wm * 16 + (lane & 15);
                uint32_t off = (uint32_t)row * 144 + ks * 32 + ((lane >> 4) << 4);
                ldm4(q_, uQ + off);
            }
            #pragma unroll
            for (int p = 0; p < 2; p++) {
                int row = wn * 32 + p * 16 + (lane & 7) + ((lane >> 4) & 1) * 8;
                uint32_t off = (uint32_t)row * 144 + ks * 32 + (((lane >> 3) & 1) << 4);
                ldm4(k_[p], uK + off);
            }
            #pragma unroll
            for (int nt = 0; nt < 4; nt++)
                mma16816(acc[nt], q_, &k_[nt >> 1][(nt & 1) * 2]);
        }

        int r0 = wm * 16 + (lane >> 2);
        #pragma unroll
        for (int nt = 0; nt < 4; nt++) {
            int col = kt + wn * 32 + nt * 8 + (lane & 3) * 2;
            if (col < L_)     S[r0 * SST + col]           = acc[nt][0];
            if (col + 1 < L_) S[r0 * SST + col + 1]       = acc[nt][1];
            if (col < L_)     S[(r0 + 8) * SST + col]     = acc[nt][2];
            if (col + 1 < L_) S[(r0 + 8) * SST + col + 1] = acc[nt][3];
        }
        __syncthreads();
    }

    // overlap: start V tile 0 load during softmax
    prefetch_t(g_vb, 0, 0);

    // ---- softmax + attn write (warp per 4 rows) ----
    for (int r = wid * 4; r < wid * 4 + 4; r++) {
        int l = q0 + r;
        if (l >= L_) continue;
        float* Sr = S + r * SST;
        float m = -1e30f;
        for (int j = lane; j < L_; j += 32) m = fmaxf(m, Sr[j]);
        #pragma unroll
        for (int o = 16; o; o >>= 1) m = fmaxf(m, __shfl_xor_sync(0xffffffffu, m, o));
        float ssum = 0.f;
        for (int j = lane; j < L_; j += 32) { float e = __expf(Sr[j] - m); Sr[j] = e; ssum += e; }
        #pragma unroll
        for (int o = 16; o; o >>= 1) ssum += __shfl_xor_sync(0xffffffffu, ssum, o);
        float inv = 1.f / ssum;
        size_t abase = ((size_t)(b * H_ + h) * L_ + l) * L_;
        for (int j = lane; j < L_; j += 32) {
            float p = Sr[j] * inv;
            Sr[j] = p;
            if (attn_out) attn_out[abase + j] = p;
        }
    }
    __syncthreads();

    // ---- phase 2: O = P.V ----
    float acc2[2][4];
    #pragma unroll
    for (int i = 0; i < 2; i++)
        #pragma unroll
        for (int c = 0; c < 4; c++) acc2[i][c] = 0.f;

    for (int t9 = 0; t9 < NTILE; t9++) {
        if (t9 + 1 < NTILE) prefetch_t(g_vb, (t9 + 1) * 128, (t9 + 1) & 1);
        int kt = t9 * 128;
        #pragma unroll
        for (int t = 0; t < 16; t++) {
            int idx = tid + t * 256;
            int r = idx >> 7, c = idx & 127;
            int col = kt + c;
            float p = (col < L_) ? S[r * SST + col] : 0.f;
            Pb[r * 136 + c] = __float2half_rn(p);
        }
        if (t9 + 1 < NTILE) asm volatile("cp.async.wait_group 1;");
        else                asm volatile("cp.async.wait_group 0;");
        __syncthreads();
        uint32_t uV = uKV + (t9 & 1) * KVSTG;

        #pragma unroll
        for (int ks = 0; ks < 8; ks++) {
            uint32_t p_[4], v_[4];
            {
                int row = wm * 16 + (lane & 15);
                uint32_t off = (uint32_t)row * 272 + ks * 32 + ((lane >> 4) << 4);
                ldm4(p_, uP + off);
            }
            {
                int row = ks * 16 + (lane & 15);
                uint32_t off = (uint32_t)row * 144 + wn * 32 + ((lane >> 4) << 4);
                ldm4t(v_, uV + off);
            }
            #pragma unroll
            for (int nt = 0; nt < 2; nt++)
                mma16816(acc2[nt], p_, &v_[nt * 2]);
        }
        __syncthreads();
    }

    // output -> fp16 (FC GEMM input)
    #pragma unroll
    for (int half = 0; half < 2; half++) {
        int r = wm * 16 + (lane >> 2) + half * 8;
        int l = q0 + r;
        if (l >= L_) continue;
        #pragma unroll
        for (int nt = 0; nt < 2; nt++) {
            int d = wn * 16 + nt * 8 + (lane & 3) * 2;
            size_t go = headq + (size_t)l * 1024 + d;
            *reinterpret_cast<ushort2*>(g_aob + go) = make_ushort2(
                h2u(__float2half_rn(acc2[nt][half * 2 + 0])),
                h2u(__float2half_rn(acc2[nt][half * 2 + 1])));
        }
    }
}

// =======================================================================
// launch
// =======================================================================
extern "C" void kernel_launch(void* const* d_in, const int* in_sizes, int n_in,
                              void* d_out, int out_size)
{
    const float* x    = (const float*)d_in[0];
    const float* wq0  = (const float*)d_in[1];
    const float* wq1  = (const float*)d_in[2];
    const float* wk0  = (const float*)d_in[3];
    const float* wk1  = (const float*)d_in[4];
    const float* wv0  = (const float*)d_in[5];
    const float* wv1  = (const float*)d_in[6];
    const float* fc_w = (const float*)d_in[7];
    const float* fc_b = (const float*)d_in[8];
    const float* ln_g = (const float*)d_in[9];
    const float* ln_b = (const float*)d_in[10];
    float* out = (float*)d_out;

    hf *p_xb, *p_qb, *p_kb, *p_vb, *p_aob, *p_wt;
    cudaGetSymbolAddress((void**)&p_xb,  g_xb);
    cudaGetSymbolAddress((void**)&p_qb,  g_qb);
    cudaGetSymbolAddress((void**)&p_kb,  g_kb);
    cudaGetSymbolAddress((void**)&p_vb,  g_vb);
    cudaGetSymbolAddress((void**)&p_aob, g_aob);
    cudaGetSymbolAddress((void**)&p_wt,  g_wt);

    float* attn_ptr = ((size_t)out_size >= OUT_ELEMS + ATTN_ELEMS)
                        ? (out + OUT_ELEMS) : nullptr;

    cudaFuncSetAttribute(mma_gemm, cudaFuncAttributeMaxDynamicSharedMemorySize, 2 * GSTG);
    cudaFuncSetAttribute(attn_mma, cudaFuncAttributeMaxDynamicSharedMemorySize, ATTN_SMEM);
    cudaFuncSetAttribute(seg_fix2, cudaFuncAttributeMaxDynamicSharedMemorySize, SEG_SMEM);

    // 1) LayerNorm (f32 + fp16)
    ln_kernel<<<M_, 256>>>(x, ln_g, ln_b);

    // 2) transpose+convert all 4 weights in one launch
    tconv4_kernel<<<dim3(32, 32, 4), 256>>>(wq0, wk0, wv0, fc_w);

    // 3) fused QKV projections (fp16 epilogue, Q pre-scaled)
    dim3 gq(8, (M_ + 127) / 128, 3);
    mma_gemm<<<gq, 256, 2 * GSTG>>>(p_xb, p_wt, nullptr, nullptr, nullptr,
                                    p_qb, p_kb, p_vb, M_);

    // 4) exact fp32 fix for the 24 weight-set-1 rows (parallel GEMV)
    seg_fix2<<<dim3(32, 3), 256, SEG_SMEM>>>(wq1, wk1, wv1);

    // 5) tensorized attention (writes attn + fp16 ao)
    attn_mma<<<dim3((L_ + 31) / 32, H_, B_), 256, ATTN_SMEM>>>(attn_ptr);

    // 6) FC (+bias+residual) -> out
    dim3 gf(8, (M_ + 127) / 128, 1);
    mma_gemm<<<gf, 256, 2 * GSTG>>>(p_aob, p_wt + 3 * (size_t)WSZ,
                                    out, fc_b, x,
                                    nullptr, nullptr, nullptr, M_);
}

// round 15
// speedup vs baseline: 1.4662x; 1.1463x over previous
#include <cuda_runtime.h>
#include <cuda_fp16.h>
#include <cstdint>

#define B_ 8
#define L_ 1030
#define D_ 1024
#define H_ 16
#define M_ (B_*L_)          // 8240
#define WSZ (1024*1024)

typedef __half hf;

static const size_t OUT_ELEMS  = (size_t)M_ * D_;              // 8,437,760
static const size_t ATTN_ELEMS = (size_t)B_ * H_ * L_ * L_;    // 135,795,200

// Scratch (device globals)
__device__ hf g_xb[M_*D_];                  // fp16 LN output (GEMM A)
__device__ hf g_fix[24*1024];               // gathered fix rows (fp16)
__device__ hf g_qb[M_*D_];                  // fp16 Q (pre-scaled 0.125)
__device__ hf g_kb[M_*D_];
__device__ hf g_vb[M_*D_];
__device__ hf g_aob[M_*D_];                 // fp16 attention output
__device__ hf g_wt[7*WSZ];                  // transposed fp16 weights [N][K]
                                            // 0:wq0 1:wk0 2:wv0 3:fc 4:wq1 5:wk1 6:wv1

// =======================================================================
// helpers
// =======================================================================
static __device__ __forceinline__ uint32_t smem_u32(const void* p) {
    uint32_t a;
    asm("{ .reg .u64 t; cvta.to.shared.u64 t, %1; cvt.u32.u64 %0, t; }"
        : "=r"(a) : "l"(p));
    return a;
}
static __device__ __forceinline__ void ldm4(uint32_t* r, uint32_t addr) {
    asm volatile("ldmatrix.sync.aligned.m8n8.x4.shared.b16 {%0,%1,%2,%3}, [%4];"
        : "=r"(r[0]), "=r"(r[1]), "=r"(r[2]), "=r"(r[3]) : "r"(addr));
}
static __device__ __forceinline__ void ldm4t(uint32_t* r, uint32_t addr) {
    asm volatile("ldmatrix.sync.aligned.m8n8.x4.trans.shared.b16 {%0,%1,%2,%3}, [%4];"
        : "=r"(r[0]), "=r"(r[1]), "=r"(r[2]), "=r"(r[3]) : "r"(addr));
}
static __device__ __forceinline__ void mma16816(float* c, const uint32_t* a,
                                                const uint32_t* b) {
    asm volatile("mma.sync.aligned.m16n8k16.row.col.f32.f16.f16.f32 "
        "{%0,%1,%2,%3}, {%4,%5,%6,%7}, {%8,%9}, {%0,%1,%2,%3};"
        : "+f"(c[0]), "+f"(c[1]), "+f"(c[2]), "+f"(c[3])
        : "r"(a[0]), "r"(a[1]), "r"(a[2]), "r"(a[3]), "r"(b[0]), "r"(b[1]));
}
static __device__ __forceinline__ void cpa(uint32_t dst, const void* src, int sz) {
    asm volatile("cp.async.cg.shared.global [%0], [%1], 16, %2;"
                 :: "r"(dst), "l"(src), "r"(sz));
}
static __device__ __forceinline__ void cpa_commit() {
    asm volatile("cp.async.commit_group;");
}
static __device__ __forceinline__ unsigned short h2u(hf v) {
    return __half_as_ushort(v);
}

// =======================================================================
// LayerNorm: writes fp16 xb; also gathers the 24 fix rows into g_fix
// =======================================================================
__global__ void __launch_bounds__(256) ln_kernel(const float* __restrict__ x,
                                                 const float* __restrict__ gam,
                                                 const float* __restrict__ bet)
{
    int row = blockIdx.x;
    int t = threadIdx.x;
    const float4* xr = reinterpret_cast<const float4*>(x + (size_t)row * D_);
    float4 v = xr[t];
    float s  = v.x + v.y + v.z + v.w;
    float ss = v.x*v.x + v.y*v.y + v.z*v.z + v.w*v.w;
    __shared__ float rs[8], rss[8], stat[2];
    #pragma unroll
    for (int o = 16; o; o >>= 1) {
        s  += __shfl_xor_sync(0xffffffffu, s,  o);
        ss += __shfl_xor_sync(0xffffffffu, ss, o);
    }
    if ((t & 31) == 0) { rs[t >> 5] = s; rss[t >> 5] = ss; }
    __syncthreads();
    if (t == 0) {
        float S = 0.f, SS = 0.f;
        #pragma unroll
        for (int i = 0; i < 8; i++) { S += rs[i]; SS += rss[i]; }
        float mu  = S / (float)D_;
        float var = SS / (float)D_ - mu * mu;
        stat[0] = mu;
        stat[1] = rsqrtf(var + 1e-6f);
    }
    __syncthreads();
    float mu = stat[0], inv = stat[1];
    float4 g4 = reinterpret_cast<const float4*>(gam)[t];
    float4 b4 = reinterpret_cast<const float4*>(bet)[t];
    float4 o;
    o.x = (v.x - mu) * inv * g4.x + b4.x;
    o.y = (v.y - mu) * inv * g4.y + b4.y;
    o.z = (v.z - mu) * inv * g4.z + b4.z;
    o.w = (v.w - mu) * inv * g4.w + b4.w;
    size_t base = (size_t)row * D_ + t * 4;
    ushort4 hv = make_ushort4(
        h2u(__float2half_rn(o.x)), h2u(__float2half_rn(o.y)),
        h2u(__float2half_rn(o.z)), h2u(__float2half_rn(o.w)));
    *reinterpret_cast<ushort4*>(g_xb + base) = hv;
    int lrow = row % L_;
    if (lrow >= L_ - 3) {
        int fidx = (row / L_) * 3 + (lrow - (L_ - 3));
        *reinterpret_cast<ushort4*>(g_fix + (size_t)fidx * 1024 + t * 4) = hv;
    }
}

// =======================================================================
// transpose + convert, all 7 weights in one launch (z selects)
// =======================================================================
__global__ void __launch_bounds__(256) tconv7_kernel(
    const float* __restrict__ w0, const float* __restrict__ w1,
    const float* __restrict__ w2, const float* __restrict__ w3,
    const float* __restrict__ w4, const float* __restrict__ w5,
    const float* __restrict__ w6)
{
    __shared__ float sm[32][33];
    int z = blockIdx.z;
    const float* W = (z == 0) ? w0 : (z == 1) ? w1 : (z == 2) ? w2 :
                     (z == 3) ? w3 : (z == 4) ? w4 : (z == 5) ? w5 : w6;
    hf* tw = g_wt + (size_t)z * WSZ;
    int c0 = blockIdx.x * 32, r0 = blockIdx.y * 32;
    int tx = threadIdx.x & 31, ty = threadIdx.x >> 5;
    #pragma unroll
    for (int k = 0; k < 32; k += 8)
        sm[ty + k][tx] = W[(size_t)(r0 + ty + k) * 1024 + c0 + tx];
    __syncthreads();
    #pragma unroll
    for (int k = 0; k < 32; k += 8) {
        float v = sm[tx][ty + k];
        int n = c0 + ty + k, kk = r0 + tx;
        tw[(size_t)n * 1024 + kk] = __float2half_rn(v);
    }
}

// =======================================================================
// single-fp16 HMMA GEMM, cp.async double-buffered, BK=64.
// Tile 128x128, 8 warps (4 M x 2 N), warp tile 32x64.
// fixmap!=0: epilogue scatters row r -> (r/3)*L + (L-3) + r%3
// =======================================================================
#define GSTG 36864
__global__ void __launch_bounds__(256) mma_gemm(
    const hf* __restrict__ A, const hf* __restrict__ Bw_,
    float* __restrict__ Cf, const float* __restrict__ bias,
    const float* __restrict__ resid,
    hf* Q_b, hf* K_b, hf* V_b, int M, int fixmap)
{
    extern __shared__ char smem[];
    const uint32_t sb = smem_u32(smem);

    const int tid = threadIdx.x;
    const int wid = tid >> 5, lane = tid & 31;
    const int wm = wid & 3, wn = wid >> 2;
    const int m0 = blockIdx.y * 128, n0 = blockIdx.x * 128;
    const int z = blockIdx.z;

    const hf* Bw = Bw_ + (size_t)z * WSZ;
    hf* Ob = (z == 0) ? Q_b : (z == 1) ? K_b : V_b;
    const float scale = (z == 0) ? 0.125f : 1.0f;

    float acc[2][8][4];
    #pragma unroll
    for (int i = 0; i < 2; i++)
        #pragma unroll
        for (int j = 0; j < 8; j++)
            #pragma unroll
            for (int c = 0; c < 4; c++) acc[i][j][c] = 0.f;

    auto prefetch = [&](int kt, int stg) {
        uint32_t base = sb + stg * GSTG;
        #pragma unroll
        for (int t = 0; t < 4; t++) {
            int idx = tid + t * 256;
            int r = idx >> 3;
            int cb = (idx & 7) * 16;
            uint32_t so = (uint32_t)r * 144 + cb;
            int arow = m0 + r;
            int sz = (arow < M) ? 16 : 0;
            int ar = (arow < M) ? arow : 0;
            cpa(base + so, (const char*)(A + (size_t)ar * 1024 + kt) + cb, sz);
            cpa(base + 18432 + so, (const char*)(Bw + (size_t)(n0 + r) * 1024 + kt) + cb, 16);
        }
        cpa_commit();
    };

    prefetch(0, 0);

    for (int it = 0; it < 16; it++) {
        if (it + 1 < 16) {
            prefetch((it + 1) * 64, (it + 1) & 1);
            asm volatile("cp.async.wait_group 1;");
        } else {
            asm volatile("cp.async.wait_group 0;");
        }
        __syncthreads();

        uint32_t st = sb + (it & 1) * GSTG;
        uint32_t sA = st, sB = st + 18432;

        #pragma unroll
        for (int ks = 0; ks < 4; ks++) {
            uint32_t a_[2][4], b_[4][4];
            #pragma unroll
            for (int mt = 0; mt < 2; mt++) {
                int row = wm * 32 + mt * 16 + (lane & 15);
                uint32_t off = (uint32_t)row * 144 + ks * 32 + ((lane >> 4) << 4);
                ldm4(a_[mt], sA + off);
            }
            #pragma unroll
            for (int p = 0; p < 4; p++) {
                int row = wn * 64 + p * 16 + (lane & 7) + ((lane >> 4) & 1) * 8;
                uint32_t off = (uint32_t)row * 144 + ks * 32 + (((lane >> 3) & 1) << 4);
                ldm4(b_[p], sB + off);
            }
            #pragma unroll
            for (int mt = 0; mt < 2; mt++)
                #pragma unroll
                for (int nt = 0; nt < 8; nt++)
                    mma16816(acc[mt][nt], a_[mt], &b_[nt >> 1][(nt & 1) * 2]);
        }
        __syncthreads();
    }

    #pragma unroll
    for (int mt = 0; mt < 2; mt++) {
        #pragma unroll
        for (int half = 0; half < 2; half++) {
            int row = m0 + wm * 32 + mt * 16 + (lane >> 2) + half * 8;
            if (row >= M) continue;
            int orow = fixmap ? ((row / 3) * L_ + (L_ - 3) + row % 3) : row;
            #pragma unroll
            for (int nt = 0; nt < 8; nt++) {
                int col = n0 + wn * 64 + nt * 8 + (lane & 3) * 2;
                float vx = acc[mt][nt][half * 2 + 0];
                float vy = acc[mt][nt][half * 2 + 1];
                size_t go = (size_t)orow * 1024 + col;
                if (Cf) {
                    if (bias) { vx += bias[col]; vy += bias[col + 1]; }
                    float2 v2; v2.x = vx; v2.y = vy;
                    if (resid) {
                        float2 rv = *reinterpret_cast<const float2*>(resid + go);
                        v2.x += rv.x; v2.y += rv.y;
                    }
                    *reinterpret_cast<float2*>(Cf + go) = v2;
                } else {
                    *reinterpret_cast<ushort2*>(Ob + go) = make_ushort2(
                        h2u(__float2half_rn(vx * scale)),
                        h2u(__float2half_rn(vy * scale)));
                }
            }
        }
    }
}

// =======================================================================
// tensorized fused attention (32 query rows, 8 warps 2Mx4N,
// cp.async double-buffered K/V, fp16 single-term)
// =======================================================================
#define SST 1032
#define OFF_Q  132096
#define OFF_KV (OFF_Q + 32*72*2)            // 136704
#define KVSTG  18432
#define OFF_P  (OFF_KV + 2*KVSTG)           // 173568
#define ATTN_SMEM (OFF_P + 32*136*2)        // 182272
#define NTILE 9

__global__ void __launch_bounds__(256) attn_mma(float* __restrict__ attn_out)
{
    extern __shared__ char sm[];
    float* S = reinterpret_cast<float*>(sm);
    hf* Qb = reinterpret_cast<hf*>(sm + OFF_Q);
    hf* Pb = reinterpret_cast<hf*>(sm + OFF_P);
    const uint32_t uQ = smem_u32(Qb);
    const uint32_t uKV = smem_u32(sm + OFF_KV);
    const uint32_t uP = smem_u32(Pb);

    const int tid = threadIdx.x;
    const int wid = tid >> 5, lane = tid & 31;
    const int wm = wid & 1, wn = wid >> 1;      // 2 (M) x 4 (N)
    const int qt = blockIdx.x, h = blockIdx.y, b = blockIdx.z;
    const int q0 = qt * 32;
    const size_t headq = (size_t)b * L_ * 1024 + h * 64;

    auto prefetch_t = [&](const hf* src, int kt, int stg) {
        uint32_t base = uKV + stg * KVSTG;
        #pragma unroll
        for (int t = 0; t < 4; t++) {
            int idx = tid + t * 256;
            int r = idx >> 3;
            int cb = (idx & 7) * 16;
            int l = kt + r;
            int sz = (l < L_) ? 16 : 0;
            int lr = (l < L_) ? l : 0;
            cpa(base + (uint32_t)r * 144 + cb,
                (const char*)(src + headq + (size_t)lr * 1024) + cb, sz);
        }
        cpa_commit();
    };

    prefetch_t(g_kb, 0, 0);

    // ---- load Q (pre-scaled fp16) ----
    #pragma unroll
    for (int t = 0; t < 2; t++) {
        int idx = tid + t * 256;
        int r = idx >> 4, c4 = (idx & 15) * 4;
        int l = q0 + r;
        ushort4 v = make_ushort4(0, 0, 0, 0);
        if (l < L_)
            v = *reinterpret_cast<const ushort4*>(g_qb + headq + (size_t)l * 1024 + c4);
        *reinterpret_cast<ushort4*>(Qb + r * 72 + c4) = v;
    }

    // ---- phase 1: S = Q.K^T ----
    for (int t9 = 0; t9 < NTILE; t9++) {
        if (t9 + 1 < NTILE) {
            prefetch_t(g_kb, (t9 + 1) * 128, (t9 + 1) & 1);
            asm volatile("cp.async.wait_group 1;");
        } else {
            asm volatile("cp.async.wait_group 0;");
        }
        __syncthreads();
        uint32_t uK = uKV + (t9 & 1) * KVSTG;
        int kt = t9 * 128;

        float acc[4][4];
        #pragma unroll
        for (int i = 0; i < 4; i++)
            #pragma unroll
            for (int c = 0; c < 4; c++) acc[i][c] = 0.f;

        #pragma unroll
        for (int ks = 0; ks < 4; ks++) {
            uint32_t q_[4], k_[2][4];
            {
                int row = wm * 16 + (lane & 15);
                uint32_t off = (uint32_t)row * 144 + ks * 32 + ((lane >> 4) << 4);
                ldm4(q_, uQ + off);
            }
            #pragma unroll
            for (int p = 0; p < 2; p++) {
                int row = wn * 32 + p * 16 + (lane & 7) + ((lane >> 4) & 1) * 8;
                uint32_t off = (uint32_t)row * 144 + ks * 32 + (((lane >> 3) & 1) << 4);
                ldm4(k_[p], uK + off);
            }
            #pragma unroll
            for (int nt = 0; nt < 4; nt++)
                mma16816(acc[nt], q_, &k_[nt >> 1][(nt & 1) * 2]);
        }

        int r0 = wm * 16 + (lane >> 2);
        #pragma unroll
        for (int nt = 0; nt < 4; nt++) {
            int col = kt + wn * 32 + nt * 8 + (lane & 3) * 2;
            if (col < L_)     S[r0 * SST + col]           = acc[nt][0];
            if (col + 1 < L_) S[r0 * SST + col + 1]       = acc[nt][1];
            if (col < L_)     S[(r0 + 8) * SST + col]     = acc[nt][2];
            if (col + 1 < L_) S[(r0 + 8) * SST + col + 1] = acc[nt][3];
        }
        __syncthreads();
    }

    // overlap: start V tile 0 load during softmax
    prefetch_t(g_vb, 0, 0);

    // ---- softmax + attn write (warp per 4 rows) ----
    for (int r = wid * 4; r < wid * 4 + 4; r++) {
        int l = q0 + r;
        if (l >= L_) continue;
        float* Sr = S + r * SST;
        float m = -1e30f;
        for (int j = lane; j < L_; j += 32) m = fmaxf(m, Sr[j]);
        #pragma unroll
        for (int o = 16; o; o >>= 1) m = fmaxf(m, __shfl_xor_sync(0xffffffffu, m, o));
        float ssum = 0.f;
        for (int j = lane; j < L_; j += 32) { float e = __expf(Sr[j] - m); Sr[j] = e; ssum += e; }
        #pragma unroll
        for (int o = 16; o; o >>= 1) ssum += __shfl_xor_sync(0xffffffffu, ssum, o);
        float inv = 1.f / ssum;
        size_t abase = ((size_t)(b * H_ + h) * L_ + l) * L_;
        for (int j = lane; j < L_; j += 32) {
            float p = Sr[j] * inv;
            Sr[j] = p;
            if (attn_out) attn_out[abase + j] = p;
        }
    }
    __syncthreads();

    // ---- phase 2: O = P.V ----
    float acc2[2][4];
    #pragma unroll
    for (int i = 0; i < 2; i++)
        #pragma unroll
        for (int c = 0; c < 4; c++) acc2[i][c] = 0.f;

    for (int t9 = 0; t9 < NTILE; t9++) {
        if (t9 + 1 < NTILE) prefetch_t(g_vb, (t9 + 1) * 128, (t9 + 1) & 1);
        int kt = t9 * 128;
        #pragma unroll
        for (int t = 0; t < 16; t++) {
            int idx = tid + t * 256;
            int r = idx >> 7, c = idx & 127;
            int col = kt + c;
            float p = (col < L_) ? S[r * SST + col] : 0.f;
            Pb[r * 136 + c] = __float2half_rn(p);
        }
        if (t9 + 1 < NTILE) asm volatile("cp.async.wait_group 1;");
        else                asm volatile("cp.async.wait_group 0;");
        __syncthreads();
        uint32_t uV = uKV + (t9 & 1) * KVSTG;

        #pragma unroll
        for (int ks = 0; ks < 8; ks++) {
            uint32_t p_[4], v_[4];
            {
                int row = wm * 16 + (lane & 15);
                uint32_t off = (uint32_t)row * 272 + ks * 32 + ((lane >> 4) << 4);
                ldm4(p_, uP + off);
            }
            {
                int row = ks * 16 + (lane & 15);
                uint32_t off = (uint32_t)row * 144 + wn * 32 + ((lane >> 4) << 4);
                ldm4t(v_, uV + off);
            }
            #pragma unroll
            for (int nt = 0; nt < 2; nt++)
                mma16816(acc2[nt], p_, &v_[nt * 2]);
        }
        __syncthreads();
    }

    // output -> fp16 (FC GEMM input)
    #pragma unroll
    for (int half = 0; half < 2; half++) {
        int r = wm * 16 + (lane >> 2) + half * 8;
        int l = q0 + r;
        if (l >= L_) continue;
        #pragma unroll
        for (int nt = 0; nt < 2; nt++) {
            int d = wn * 16 + nt * 8 + (lane & 3) * 2;
            size_t go = headq + (size_t)l * 1024 + d;
            *reinterpret_cast<ushort2*>(g_aob + go) = make_ushort2(
                h2u(__float2half_rn(acc2[nt][half * 2 + 0])),
                h2u(__float2half_rn(acc2[nt][half * 2 + 1])));
        }
    }
}

// =======================================================================
// launch
// =======================================================================
extern "C" void kernel_launch(void* const* d_in, const int* in_sizes, int n_in,
                              void* d_out, int out_size)
{
    const float* x    = (const float*)d_in[0];
    const float* wq0  = (const float*)d_in[1];
    const float* wq1  = (const float*)d_in[2];
    const float* wk0  = (const float*)d_in[3];
    const float* wk1  = (const float*)d_in[4];
    const float* wv0  = (const float*)d_in[5];
    const float* wv1  = (const float*)d_in[6];
    const float* fc_w = (const float*)d_in[7];
    const float* fc_b = (const float*)d_in[8];
    const float* ln_g = (const float*)d_in[9];
    const float* ln_b = (const float*)d_in[10];
    float* out = (float*)d_out;

    hf *p_xb, *p_fix, *p_qb, *p_kb, *p_vb, *p_aob, *p_wt;
    cudaGetSymbolAddress((void**)&p_xb,  g_xb);
    cudaGetSymbolAddress((void**)&p_fix, g_fix);
    cudaGetSymbolAddress((void**)&p_qb,  g_qb);
    cudaGetSymbolAddress((void**)&p_kb,  g_kb);
    cudaGetSymbolAddress((void**)&p_vb,  g_vb);
    cudaGetSymbolAddress((void**)&p_aob, g_aob);
    cudaGetSymbolAddress((void**)&p_wt,  g_wt);

    float* attn_ptr = ((size_t)out_size >= OUT_ELEMS + ATTN_ELEMS)
                        ? (out + OUT_ELEMS) : nullptr;

    cudaFuncSetAttribute(mma_gemm, cudaFuncAttributeMaxDynamicSharedMemorySize, 2 * GSTG);
    cudaFuncSetAttribute(attn_mma, cudaFuncAttributeMaxDynamicSharedMemorySize, ATTN_SMEM);

    // 1) LayerNorm (fp16 + fix-row gather)
    ln_kernel<<<M_, 256>>>(x, ln_g, ln_b);

    // 2) transpose+convert all 7 weights in one launch
    tconv7_kernel<<<dim3(32, 32, 7), 256>>>(wq0, wk0, wv0, fc_w, wq1, wk1, wv1);

    // 3) fused QKV projections (fp16 epilogue, Q pre-scaled)
    dim3 gq(8, (M_ + 127) / 128, 3);
    mma_gemm<<<gq, 256, 2 * GSTG>>>(p_xb, p_wt, nullptr, nullptr, nullptr,
                                    p_qb, p_kb, p_vb, M_, 0);

    // 4) fix rows via HMMA on weight set 1 (scatter epilogue)
    dim3 gfx(8, 1, 3);
    mma_gemm<<<gfx, 256, 2 * GSTG>>>(p_fix, p_wt + 4 * (size_t)WSZ,
                                     nullptr, nullptr, nullptr,
                                     p_qb, p_kb, p_vb, 24, 1);

    // 5) tensorized attention (writes attn + fp16 ao)
    attn_mma<<<dim3((L_ + 31) / 32, H_, B_), 256, ATTN_SMEM>>>(attn_ptr);

    // 6) FC (+bias+residual) -> out
    dim3 gf(8, (M_ + 127) / 128, 1);
    mma_gemm<<<gf, 256, 2 * GSTG>>>(p_aob, p_wt + 3 * (size_t)WSZ,
                                    out, fc_b, x,
                                    nullptr, nullptr, nullptr, M_, 0);
}

// round 16
// speedup vs baseline: 1.6675x; 1.1373x over previous
#include <cuda_runtime.h>
#include <cuda_fp16.h>
#include <cstdint>

#define B_ 8
#define L_ 1030
#define D_ 1024
#define H_ 16
#define M_ (B_*L_)          // 8240
#define WSZ (1024*1024)

typedef __half hf;

static const size_t OUT_ELEMS  = (size_t)M_ * D_;              // 8,437,760
static const size_t ATTN_ELEMS = (size_t)B_ * H_ * L_ * L_;    // 135,795,200

// Scratch (device globals)
__device__ hf g_xb[M_*D_];                  // fp16 LN output (GEMM A)
__device__ hf g_fix[24*1024];               // gathered fix rows (fp16)
__device__ hf g_qb[M_*D_];                  // fp16 Q (pre-scaled 0.125)
__device__ hf g_kb[M_*D_];
__device__ hf g_vb[M_*D_];
__device__ hf g_aob[M_*D_];                 // fp16 attention output
__device__ hf g_wt[7*WSZ];                  // transposed fp16 weights [N][K]
                                            // 0:wq0 1:wk0 2:wv0 3:fc 4:wq1 5:wk1 6:wv1

// =======================================================================
// helpers
// =======================================================================
static __device__ __forceinline__ uint32_t smem_u32(const void* p) {
    uint32_t a;
    asm("{ .reg .u64 t; cvta.to.shared.u64 t, %1; cvt.u32.u64 %0, t; }"
        : "=r"(a) : "l"(p));
    return a;
}
static __device__ __forceinline__ void ldm4(uint32_t* r, uint32_t addr) {
    asm volatile("ldmatrix.sync.aligned.m8n8.x4.shared.b16 {%0,%1,%2,%3}, [%4];"
        : "=r"(r[0]), "=r"(r[1]), "=r"(r[2]), "=r"(r[3]) : "r"(addr));
}
static __device__ __forceinline__ void ldm4t(uint32_t* r, uint32_t addr) {
    asm volatile("ldmatrix.sync.aligned.m8n8.x4.trans.shared.b16 {%0,%1,%2,%3}, [%4];"
        : "=r"(r[0]), "=r"(r[1]), "=r"(r[2]), "=r"(r[3]) : "r"(addr));
}
static __device__ __forceinline__ void mma16816(float* c, const uint32_t* a,
                                                const uint32_t* b) {
    asm volatile("mma.sync.aligned.m16n8k16.row.col.f32.f16.f16.f32 "
        "{%0,%1,%2,%3}, {%4,%5,%6,%7}, {%8,%9}, {%0,%1,%2,%3};"
        : "+f"(c[0]), "+f"(c[1]), "+f"(c[2]), "+f"(c[3])
        : "r"(a[0]), "r"(a[1]), "r"(a[2]), "r"(a[3]), "r"(b[0]), "r"(b[1]));
}
static __device__ __forceinline__ void cpa(uint32_t dst, const void* src, int sz) {
    asm volatile("cp.async.cg.shared.global [%0], [%1], 16, %2;"
                 :: "r"(dst), "l"(src), "r"(sz));
}
static __device__ __forceinline__ void cpa_commit() {
    asm volatile("cp.async.commit_group;");
}
static __device__ __forceinline__ unsigned short h2u(hf v) {
    return __half_as_ushort(v);
}

// =======================================================================
// LayerNorm: writes fp16 xb; also gathers the 24 fix rows into g_fix
// =======================================================================
__global__ void __launch_bounds__(256) ln_kernel(const float* __restrict__ x,
                                                 const float* __restrict__ gam,
                                                 const float* __restrict__ bet)
{
    int row = blockIdx.x;
    int t = threadIdx.x;
    const float4* xr = reinterpret_cast<const float4*>(x + (size_t)row * D_);
    float4 v = xr[t];
    float s  = v.x + v.y + v.z + v.w;
    float ss = v.x*v.x + v.y*v.y + v.z*v.z + v.w*v.w;
    __shared__ float rs[8], rss[8], stat[2];
    #pragma unroll
    for (int o = 16; o; o >>= 1) {
        s  += __shfl_xor_sync(0xffffffffu, s,  o);
        ss += __shfl_xor_sync(0xffffffffu, ss, o);
    }
    if ((t & 31) == 0) { rs[t >> 5] = s; rss[t >> 5] = ss; }
    __syncthreads();
    if (t == 0) {
        float S = 0.f, SS = 0.f;
        #pragma unroll
        for (int i = 0; i < 8; i++) { S += rs[i]; SS += rss[i]; }
        float mu  = S / (float)D_;
        float var = SS / (float)D_ - mu * mu;
        stat[0] = mu;
        stat[1] = rsqrtf(var + 1e-6f);
    }
    __syncthreads();
    float mu = stat[0], inv = stat[1];
    float4 g4 = reinterpret_cast<const float4*>(gam)[t];
    float4 b4 = reinterpret_cast<const float4*>(bet)[t];
    float4 o;
    o.x = (v.x - mu) * inv * g4.x + b4.x;
    o.y = (v.y - mu) * inv * g4.y + b4.y;
    o.z = (v.z - mu) * inv * g4.z + b4.z;
    o.w = (v.w - mu) * inv * g4.w + b4.w;
    size_t base = (size_t)row * D_ + t * 4;
    ushort4 hv = make_ushort4(
        h2u(__float2half_rn(o.x)), h2u(__float2half_rn(o.y)),
        h2u(__float2half_rn(o.z)), h2u(__float2half_rn(o.w)));
    *reinterpret_cast<ushort4*>(g_xb + base) = hv;
    int lrow = row % L_;
    if (lrow >= L_ - 3) {
        int fidx = (row / L_) * 3 + (lrow - (L_ - 3));
        *reinterpret_cast<ushort4*>(g_fix + (size_t)fidx * 1024 + t * 4) = hv;
    }
}

// =======================================================================
// transpose + convert, all 7 weights in one launch (z selects)
// =======================================================================
__global__ void __launch_bounds__(256) tconv7_kernel(
    const float* __restrict__ w0, const float* __restrict__ w1,
    const float* __restrict__ w2, const float* __restrict__ w3,
    const float* __restrict__ w4, const float* __restrict__ w5,
    const float* __restrict__ w6)
{
    __shared__ float sm[32][33];
    int z = blockIdx.z;
    const float* W = (z == 0) ? w0 : (z == 1) ? w1 : (z == 2) ? w2 :
                     (z == 3) ? w3 : (z == 4) ? w4 : (z == 5) ? w5 : w6;
    hf* tw = g_wt + (size_t)z * WSZ;
    int c0 = blockIdx.x * 32, r0 = blockIdx.y * 32;
    int tx = threadIdx.x & 31, ty = threadIdx.x >> 5;
    #pragma unroll
    for (int k = 0; k < 32; k += 8)
        sm[ty + k][tx] = W[(size_t)(r0 + ty + k) * 1024 + c0 + tx];
    __syncthreads();
    #pragma unroll
    for (int k = 0; k < 32; k += 8) {
        float v = sm[tx][ty + k];
        int n = c0 + ty + k, kk = r0 + tx;
        tw[(size_t)n * 1024 + kk] = __float2half_rn(v);
    }
}

// =======================================================================
// single-fp16 HMMA GEMM, cp.async double-buffered, BK=64.
// Tile 128x128, 8 warps (4 M x 2 N), warp tile 32x64.
// fixmap!=0: epilogue scatters row r -> (r/3)*L + (L-3) + r%3
// =======================================================================
#define GSTG 36864
__global__ void __launch_bounds__(256) mma_gemm(
    const hf* __restrict__ A, const hf* __restrict__ Bw_,
    float* __restrict__ Cf, const float* __restrict__ bias,
    const float* __restrict__ resid,
    hf* Q_b, hf* K_b, hf* V_b, int M, int fixmap)
{
    extern __shared__ char smem[];
    const uint32_t sb = smem_u32(smem);

    const int tid = threadIdx.x;
    const int wid = tid >> 5, lane = tid & 31;
    const int wm = wid & 3, wn = wid >> 2;
    const int m0 = blockIdx.y * 128, n0 = blockIdx.x * 128;
    const int z = blockIdx.z;

    const hf* Bw = Bw_ + (size_t)z * WSZ;
    hf* Ob = (z == 0) ? Q_b : (z == 1) ? K_b : V_b;
    const float scale = (z == 0) ? 0.125f : 1.0f;

    float acc[2][8][4];
    #pragma unroll
    for (int i = 0; i < 2; i++)
        #pragma unroll
        for (int j = 0; j < 8; j++)
            #pragma unroll
            for (int c = 0; c < 4; c++) acc[i][j][c] = 0.f;

    auto prefetch = [&](int kt, int stg) {
        uint32_t base = sb + stg * GSTG;
        #pragma unroll
        for (int t = 0; t < 4; t++) {
            int idx = tid + t * 256;
            int r = idx >> 3;
            int cb = (idx & 7) * 16;
            uint32_t so = (uint32_t)r * 144 + cb;
            int arow = m0 + r;
            int sz = (arow < M) ? 16 : 0;
            int ar = (arow < M) ? arow : 0;
            cpa(base + so, (const char*)(A + (size_t)ar * 1024 + kt) + cb, sz);
            cpa(base + 18432 + so, (const char*)(Bw + (size_t)(n0 + r) * 1024 + kt) + cb, 16);
        }
        cpa_commit();
    };

    prefetch(0, 0);

    for (int it = 0; it < 16; it++) {
        if (it + 1 < 16) {
            prefetch((it + 1) * 64, (it + 1) & 1);
            asm volatile("cp.async.wait_group 1;");
        } else {
            asm volatile("cp.async.wait_group 0;");
        }
        __syncthreads();

        uint32_t st = sb + (it & 1) * GSTG;
        uint32_t sA = st, sB = st + 18432;

        #pragma unroll
        for (int ks = 0; ks < 4; ks++) {
            uint32_t a_[2][4], b_[4][4];
            #pragma unroll
            for (int mt = 0; mt < 2; mt++) {
                int row = wm * 32 + mt * 16 + (lane & 15);
                uint32_t off = (uint32_t)row * 144 + ks * 32 + ((lane >> 4) << 4);
                ldm4(a_[mt], sA + off);
            }
            #pragma unroll
            for (int p = 0; p < 4; p++) {
                int row = wn * 64 + p * 16 + (lane & 7) + ((lane >> 4) & 1) * 8;
                uint32_t off = (uint32_t)row * 144 + ks * 32 + (((lane >> 3) & 1) << 4);
                ldm4(b_[p], sB + off);
            }
            #pragma unroll
            for (int mt = 0; mt < 2; mt++)
                #pragma unroll
                for (int nt = 0; nt < 8; nt++)
                    mma16816(acc[mt][nt], a_[mt], &b_[nt >> 1][(nt & 1) * 2]);
        }
        __syncthreads();
    }

    #pragma unroll
    for (int mt = 0; mt < 2; mt++) {
        #pragma unroll
        for (int half = 0; half < 2; half++) {
            int row = m0 + wm * 32 + mt * 16 + (lane >> 2) + half * 8;
            if (row >= M) continue;
            int orow = fixmap ? ((row / 3) * L_ + (L_ - 3) + row % 3) : row;
            #pragma unroll
            for (int nt = 0; nt < 8; nt++) {
                int col = n0 + wn * 64 + nt * 8 + (lane & 3) * 2;
                float vx = acc[mt][nt][half * 2 + 0];
                float vy = acc[mt][nt][half * 2 + 1];
                size_t go = (size_t)orow * 1024 + col;
                if (Cf) {
                    if (bias) { vx += bias[col]; vy += bias[col + 1]; }
                    float2 v2; v2.x = vx; v2.y = vy;
                    if (resid) {
                        float2 rv = *reinterpret_cast<const float2*>(resid + go);
                        v2.x += rv.x; v2.y += rv.y;
                    }
                    *reinterpret_cast<float2*>(Cf + go) = v2;
                } else {
                    *reinterpret_cast<ushort2*>(Ob + go) = make_ushort2(
                        h2u(__float2half_rn(vx * scale)),
                        h2u(__float2half_rn(vy * scale)));
                }
            }
        }
    }
}

// =======================================================================
// tensorized fused attention, v2: fp16 S (stride 1040, zero-padded
// 1030..1039), register rowmax, deferred normalization, PV reads e
// directly from fp16 S via ldmatrix. 108.8KB smem -> 2 CTAs/SM.
// 32 query rows, 8 warps (2M x 4N), cp.async double-buffered K/V.
// =======================================================================
#define SSTH 1040                 // fp16 stride (2080 B/row)
#define OFF_S   0                 // 32 x 1040 hf = 66560
#define OFF_Q   66560             // 32 x 72 hf   = 4608
#define OFF_KV  71168             // 2 x 18432    = 36864
#define KVSTG   18432
#define OFF_RMP 108032            // 32 x 4 f32   = 512
#define OFF_RM  108544            // 32 f32       = 128
#define OFF_INV 108672            // 32 f32       = 128
#define ATTN_SMEM 108800
#define NTILE 9

__global__ void __launch_bounds__(256, 2) attn_mma(float* __restrict__ attn_out)
{
    extern __shared__ char sm[];
    hf* Sh = reinterpret_cast<hf*>(sm + OFF_S);
    hf* Qb = reinterpret_cast<hf*>(sm + OFF_Q);
    float* rowmaxp = reinterpret_cast<float*>(sm + OFF_RMP);
    float* rowmax  = reinterpret_cast<float*>(sm + OFF_RM);
    float* invs    = reinterpret_cast<float*>(sm + OFF_INV);
    const uint32_t uS = smem_u32(Sh);
    const uint32_t uQ = smem_u32(Qb);
    const uint32_t uKV = smem_u32(sm + OFF_KV);

    const int tid = threadIdx.x;
    const int wid = tid >> 5, lane = tid & 31;
    const int wm = wid & 1, wn = wid >> 1;      // 2 (M) x 4 (N)
    const int qt = blockIdx.x, h = blockIdx.y, b = blockIdx.z;
    const int q0 = qt * 32;
    const size_t headq = (size_t)b * L_ * 1024 + h * 64;

    auto prefetch_t = [&](const hf* src, int kt, int stg) {
        uint32_t base = uKV + stg * KVSTG;
        #pragma unroll
        for (int t = 0; t < 4; t++) {
            int idx = tid + t * 256;
            int r = idx >> 3;
            int cb = (idx & 7) * 16;
            int l = kt + r;
            int sz = (l < L_) ? 16 : 0;
            int lr = (l < L_) ? l : 0;
            cpa(base + (uint32_t)r * 144 + cb,
                (const char*)(src + headq + (size_t)lr * 1024) + cb, sz);
        }
        cpa_commit();
    };

    prefetch_t(g_kb, 0, 0);

    // ---- load Q (pre-scaled fp16) ----
    #pragma unroll
    for (int t = 0; t < 2; t++) {
        int idx = tid + t * 256;
        int r = idx >> 4, c4 = (idx & 15) * 4;
        int l = q0 + r;
        ushort4 v = make_ushort4(0, 0, 0, 0);
        if (l < L_)
            v = *reinterpret_cast<const ushort4*>(g_qb + headq + (size_t)l * 1024 + c4);
        *reinterpret_cast<ushort4*>(Qb + r * 72 + c4) = v;
    }

    // ---- phase 1: S = Q.K^T (f32 acc -> fp16 store, register rowmax) ----
    const int r0l = lane >> 2;
    float mx0 = -1e30f, mx1 = -1e30f;
    for (int t9 = 0; t9 < NTILE; t9++) {
        if (t9 + 1 < NTILE) {
            prefetch_t(g_kb, (t9 + 1) * 128, (t9 + 1) & 1);
            asm volatile("cp.async.wait_group 1;");
        } else {
            asm volatile("cp.async.wait_group 0;");
        }
        __syncthreads();
        uint32_t uK = uKV + (t9 & 1) * KVSTG;
        int kt = t9 * 128;

        float acc[4][4];
        #pragma unroll
        for (int i = 0; i < 4; i++)
            #pragma unroll
            for (int c = 0; c < 4; c++) acc[i][c] = 0.f;

        #pragma unroll
        for (int ks = 0; ks < 4; ks++) {
            uint32_t q_[4], k_[2][4];
            {
                int row = wm * 16 + (lane & 15);
                uint32_t off = (uint32_t)row * 144 + ks * 32 + ((lane >> 4) << 4);
                ldm4(q_, uQ + off);
            }
            #pragma unroll
            for (int p = 0; p < 2; p++) {
                int row = wn * 32 + p * 16 + (lane & 7) + ((lane >> 4) & 1) * 8;
                uint32_t off = (uint32_t)row * 144 + ks * 32 + (((lane >> 3) & 1) << 4);
                ldm4(k_[p], uK + off);
            }
            #pragma unroll
            for (int nt = 0; nt < 4; nt++)
                mma16816(acc[nt], q_, &k_[nt >> 1][(nt & 1) * 2]);
        }

        int rA = wm * 16 + r0l;
        #pragma unroll
        for (int nt = 0; nt < 4; nt++) {
            int col = kt + wn * 32 + nt * 8 + (lane & 3) * 2;
            if (col < SSTH) {
                bool valid = (col < L_);      // col<1030 => col+1<=1029 valid too
                __half2 v01 = valid ? __floats2half2_rn(acc[nt][0], acc[nt][1])
                                    : __floats2half2_rn(0.f, 0.f);
                __half2 v23 = valid ? __floats2half2_rn(acc[nt][2], acc[nt][3])
                                    : __floats2half2_rn(0.f, 0.f);
                *reinterpret_cast<__half2*>(Sh + rA * SSTH + col)       = v01;
                *reinterpret_cast<__half2*>(Sh + (rA + 8) * SSTH + col) = v23;
                if (valid) {
                    mx0 = fmaxf(mx0, fmaxf(acc[nt][0], acc[nt][1]));
                    mx1 = fmaxf(mx1, fmaxf(acc[nt][2], acc[nt][3]));
                }
            }
        }
        __syncthreads();
    }
    // reduce max across the 4 lanes sharing a row, then across the 4 wn groups
    mx0 = fmaxf(mx0, __shfl_xor_sync(0xffffffffu, mx0, 1));
    mx0 = fmaxf(mx0, __shfl_xor_sync(0xffffffffu, mx0, 2));
    mx1 = fmaxf(mx1, __shfl_xor_sync(0xffffffffu, mx1, 1));
    mx1 = fmaxf(mx1, __shfl_xor_sync(0xffffffffu, mx1, 2));
    if ((lane & 3) == 0) {
        int rA = wm * 16 + r0l;
        rowmaxp[rA * 4 + wn]       = mx0;
        rowmaxp[(rA + 8) * 4 + wn] = mx1;
    }
    prefetch_t(g_vb, 0, 0);          // overlap V(0) with reductions
    __syncthreads();
    if (tid < 32) {
        float m = -1e30f;
        #pragma unroll
        for (int j = 0; j < 4; j++) m = fmaxf(m, rowmaxp[tid * 4 + j]);
        rowmax[tid] = m;
    }
    __syncthreads();

    // ---- exp scan: e = exp(S-m) stored fp16 in-place, row sums -> invs ----
    for (int r = wid * 4; r < wid * 4 + 4; r++) {
        float m = rowmax[r];
        hf* Sr = Sh + r * SSTH;
        float ssum = 0.f;
        for (int j = lane; j < SSTH; j += 32) {
            float e = 0.f;
            if (j < L_) { e = __expf(__half2float(Sr[j]) - m); ssum += e; }
            Sr[j] = __float2half_rn(e);
        }
        #pragma unroll
        for (int o = 16; o; o >>= 1) ssum += __shfl_xor_sync(0xffffffffu, ssum, o);
        if (lane == 0) invs[r] = 1.f / ssum;
    }
    __syncthreads();

    // ---- phase 2: O = e.V (read e straight from Sh), 8 full tiles + k16 tail
    float acc2[2][4];
    #pragma unroll
    for (int i = 0; i < 2; i++)
        #pragma unroll
        for (int c = 0; c < 4; c++) acc2[i][c] = 0.f;

    for (int t9 = 0; t9 < NTILE; t9++) {
        if (t9 + 1 < NTILE) {
            prefetch_t(g_vb, (t9 + 1) * 128, (t9 + 1) & 1);
            asm volatile("cp.async.wait_group 1;");
        } else {
            asm volatile("cp.async.wait_group 0;");
        }
        __syncthreads();
        uint32_t uV = uKV + (t9 & 1) * KVSTG;
        int nks = (t9 < 8) ? 8 : 1;        // tail: cols 1024..1039 (zero-padded)

        for (int ks = 0; ks < nks; ks++) {
            uint32_t p_[4], v_[4];
            {
                int row = wm * 16 + (lane & 15);
                uint32_t off = (uint32_t)row * (SSTH * 2)
                             + (uint32_t)(t9 * 128 + ks * 16) * 2 + ((lane >> 4) << 4);
                ldm4(p_, uS + off);
            }
            {
                int row = ks * 16 + (lane & 15);
                uint32_t off = (uint32_t)row * 144 + wn * 32 + ((lane >> 4) << 4);
                ldm4t(v_, uV + off);
            }
            #pragma unroll
            for (int nt = 0; nt < 2; nt++)
                mma16816(acc2[nt], p_, &v_[nt * 2]);
        }
        __syncthreads();
    }

    // ---- O epilogue: scale by 1/sum -> fp16 (FC GEMM input) ----
    #pragma unroll
    for (int half = 0; half < 2; half++) {
        int r = wm * 16 + (lane >> 2) + half * 8;
        int l = q0 + r;
        if (l >= L_) continue;
        float iv = invs[r];
        #pragma unroll
        for (int nt = 0; nt < 2; nt++) {
            int d = wn * 16 + nt * 8 + (lane & 3) * 2;
            size_t go = headq + (size_t)l * 1024 + d;
            *reinterpret_cast<ushort2*>(g_aob + go) = make_ushort2(
                h2u(__float2half_rn(acc2[nt][half * 2 + 0] * iv)),
                h2u(__float2half_rn(acc2[nt][half * 2 + 1] * iv)));
        }
    }

    // ---- attn output: p = e * inv (coalesced f32 write) ----
    if (attn_out) {
        for (int r = wid * 4; r < wid * 4 + 4; r++) {
            int l = q0 + r;
            if (l >= L_) continue;
            float iv = invs[r];
            const hf* Sr = Sh + r * SSTH;
            size_t abase = ((size_t)(b * H_ + h) * L_ + l) * L_;
            for (int j = lane; j < L_; j += 32)
                attn_out[abase + j] = __half2float(Sr[j]) * iv;
        }
    }
}

// =======================================================================
// launch
// =======================================================================
extern "C" void kernel_launch(void* const* d_in, const int* in_sizes, int n_in,
                              void* d_out, int out_size)
{
    const float* x    = (const float*)d_in[0];
    const float* wq0  = (const float*)d_in[1];
    const float* wq1  = (const float*)d_in[2];
    const float* wk0  = (const float*)d_in[3];
    const float* wk1  = (const float*)d_in[4];
    const float* wv0  = (const float*)d_in[5];
    const float* wv1  = (const float*)d_in[6];
    const float* fc_w = (const float*)d_in[7];
    const float* fc_b = (const float*)d_in[8];
    const float* ln_g = (const float*)d_in[9];
    const float* ln_b = (const float*)d_in[10];
    float* out = (float*)d_out;

    hf *p_xb, *p_fix, *p_qb, *p_kb, *p_vb, *p_aob, *p_wt;
    cudaGetSymbolAddress((void**)&p_xb,  g_xb);
    cudaGetSymbolAddress((void**)&p_fix, g_fix);
    cudaGetSymbolAddress((void**)&p_qb,  g_qb);
    cudaGetSymbolAddress((void**)&p_kb,  g_kb);
    cudaGetSymbolAddress((void**)&p_vb,  g_vb);
    cudaGetSymbolAddress((void**)&p_aob, g_aob);
    cudaGetSymbolAddress((void**)&p_wt,  g_wt);

    float* attn_ptr = ((size_t)out_size >= OUT_ELEMS + ATTN_ELEMS)
                        ? (out + OUT_ELEMS) : nullptr;

    cudaFuncSetAttribute(mma_gemm, cudaFuncAttributeMaxDynamicSharedMemorySize, 2 * GSTG);
    cudaFuncSetAttribute(attn_mma, cudaFuncAttributeMaxDynamicSharedMemorySize, ATTN_SMEM);

    // 1) LayerNorm (fp16 + fix-row gather)
    ln_kernel<<<M_, 256>>>(x, ln_g, ln_b);

    // 2) transpose+convert all 7 weights in one launch
    tconv7_kernel<<<dim3(32, 32, 7), 256>>>(wq0, wk0, wv0, fc_w, wq1, wk1, wv1);

    // 3) fused QKV projections (fp16 epilogue, Q pre-scaled)
    dim3 gq(8, (M_ + 127) / 128, 3);
    mma_gemm<<<gq, 256, 2 * GSTG>>>(p_xb, p_wt, nullptr, nullptr, nullptr,
                                    p_qb, p_kb, p_vb, M_, 0);

    // 4) fix rows via HMMA on weight set 1 (scatter epilogue)
    dim3 gfx(8, 1, 3);
    mma_gemm<<<gfx, 256, 2 * GSTG>>>(p_fix, p_wt + 4 * (size_t)WSZ,
                                     nullptr, nullptr, nullptr,
                                     p_qb, p_kb, p_vb, 24, 1);

    // 5) tensorized attention v2 (2 CTAs/SM; writes attn + fp16 ao)
    attn_mma<<<dim3((L_ + 31) / 32, H_, B_), 256, ATTN_SMEM>>>(attn_ptr);

    // 6) FC (+bias+residual) -> out
    dim3 gf(8, (M_ + 127) / 128, 1);
    mma_gemm<<<gf, 256, 2 * GSTG>>>(p_aob, p_wt + 3 * (size_t)WSZ,
                                    out, fc_b, x,
                                    nullptr, nullptr, nullptr, M_, 0);
}